// round 2
// baseline (speedup 1.0000x reference)
#include <cuda_runtime.h>
#include <cstdint>

// Problem constants
#define Nn   2048
#define Mm   256
#define DQd  512
#define DMd  512
#define Pp   256

// Scratch (device globals; no allocations allowed)
__device__ float g_q[Nn * Pp];        // q projection  [N, P]
__device__ float g_sc[Nn * Mm];       // scores -> att [N, M]
__device__ float g_ctx[Nn * DMd];     // context       [N, DM]

// ---------------------------------------------------------------------------
// Generic 64x64-tile fp32 GEMM: C = act(A @ B + bias)
//  CAT=false: A = A0 [rows, K], row stride K
//  CAT=true : A = [A0 | A1] concat on k (each stride 512, switch at k=512)
// ---------------------------------------------------------------------------
template <bool CAT, bool RELU>
__global__ void __launch_bounds__(256, 2) gemm64_kernel(
    const float* __restrict__ A0, const float* __restrict__ A1,
    const float* __restrict__ B, const float* __restrict__ bias,
    float* __restrict__ C, int K, int Ncols)
{
    __shared__ float As[16][68];   // transposed: As[k][row], padded
    __shared__ float Bs[16][64];

    const int t = threadIdx.x;
    const int row0 = blockIdx.y * 64;
    const int col0 = blockIdx.x * 64;
    const int tx = t & 15;         // col group (4 cols)
    const int ty = t >> 4;         // row group (4 rows)

    const int lr = t >> 2;         // A load: row 0..63
    const int kc = t & 3;          // A load: k chunk (4 floats)
    const int kb = t >> 4;         // B load: k row 0..15
    const int cc = t & 15;         // B load: col chunk

    float acc[4][4];
#pragma unroll
    for (int i = 0; i < 4; i++)
#pragma unroll
        for (int j = 0; j < 4; j++) acc[i][j] = 0.f;

    for (int k0 = 0; k0 < K; k0 += 16) {
        const int kg = k0 + kc * 4;
        const float* asrc;
        if (CAT) {
            asrc = (kg < 512) ? (A0 + (size_t)(row0 + lr) * 512 + kg)
                              : (A1 + (size_t)(row0 + lr) * 512 + (kg - 512));
        } else {
            asrc = A0 + (size_t)(row0 + lr) * K + kg;
        }
        float4 av = *(const float4*)asrc;
        float4 bv = *(const float4*)(B + (size_t)(k0 + kb) * Ncols + col0 + cc * 4);

        __syncthreads();
        As[kc * 4 + 0][lr] = av.x;
        As[kc * 4 + 1][lr] = av.y;
        As[kc * 4 + 2][lr] = av.z;
        As[kc * 4 + 3][lr] = av.w;
        *(float4*)&Bs[kb][cc * 4] = bv;
        __syncthreads();

#pragma unroll
        for (int k = 0; k < 16; k++) {
            float4 a = *(const float4*)&As[k][ty * 4];
            float4 b = *(const float4*)&Bs[k][tx * 4];
            float aa[4] = {a.x, a.y, a.z, a.w};
            float bb[4] = {b.x, b.y, b.z, b.w};
#pragma unroll
            for (int i = 0; i < 4; i++)
#pragma unroll
                for (int j = 0; j < 4; j++) acc[i][j] += aa[i] * bb[j];
        }
    }

#pragma unroll
    for (int i = 0; i < 4; i++) {
#pragma unroll
        for (int j = 0; j < 4; j++) {
            int c = col0 + tx * 4 + j;
            float v = acc[i][j] + bias[c];
            if (RELU) v = fmaxf(v, 0.f);
            C[(size_t)(row0 + ty * 4 + i) * Ncols + c] = v;
        }
    }
}

// ---------------------------------------------------------------------------
// Scores: for flattened rows r = n*M + m,
//   scores[r] = sum_p tanh( (memory[r,:] . U[:,p]) + q[n,p] + Ub[p] ) * w[p] + wb
// CTA: 128 rows x 256 cols (full P), BK=16, 512 threads, 8x8 per thread.
// Warp w owns rows w*8..w*8+7; lane owns cols {lane*4..+3} U {128+lane*4..+3}.
// ---------------------------------------------------------------------------
__global__ void __launch_bounds__(512, 1) scores_kernel(
    const float* __restrict__ mem, const float* __restrict__ U,
    const float* __restrict__ Ub, const float* __restrict__ w,
    const float* __restrict__ wb, const float* __restrict__ q,
    float* __restrict__ scores)
{
    __shared__ float As[16][132];   // transposed A: As[k][row]
    __shared__ float Bs[16][256];
    __shared__ float qw[256];       // q[n,p] + Ub[p]
    __shared__ float ws[256];

    const int t = threadIdx.x;
    const int row0 = blockIdx.x * 128;
    const int n = row0 >> 8;                 // row0 / 256, tile never crosses n
    const int warp = t >> 5, lane = t & 31;

    if (t < 256) {
        qw[t] = q[n * Pp + t] + Ub[t];
        ws[t] = w[t];
    }

    const int lr = t >> 2;     // A load row 0..127
    const int kc = t & 3;      // A load k-chunk

    float acc[8][8];
#pragma unroll
    for (int i = 0; i < 8; i++)
#pragma unroll
        for (int j = 0; j < 8; j++) acc[i][j] = 0.f;

    const float* Abase = mem + (size_t)row0 * DMd;

    for (int k0 = 0; k0 < DMd; k0 += 16) {
        float4 av = *(const float4*)(Abase + (size_t)lr * DMd + k0 + kc * 4);
        // B tile 16x256 = 1024 float4 slots, 2 per thread
        float4 bv0 = *(const float4*)(U + (size_t)(k0 + (t >> 6)) * Pp + (t & 63) * 4);
        float4 bv1 = *(const float4*)(U + (size_t)(k0 + 8 + (t >> 6)) * Pp + (t & 63) * 4);

        __syncthreads();
        As[kc * 4 + 0][lr] = av.x;
        As[kc * 4 + 1][lr] = av.y;
        As[kc * 4 + 2][lr] = av.z;
        As[kc * 4 + 3][lr] = av.w;
        *(float4*)&Bs[(t >> 6)][(t & 63) * 4] = bv0;
        *(float4*)&Bs[8 + (t >> 6)][(t & 63) * 4] = bv1;
        __syncthreads();

#pragma unroll
        for (int k = 0; k < 16; k++) {
            float4 a0 = *(const float4*)&As[k][warp * 8];
            float4 a1 = *(const float4*)&As[k][warp * 8 + 4];
            float4 b0 = *(const float4*)&Bs[k][lane * 4];
            float4 b1 = *(const float4*)&Bs[k][128 + lane * 4];
            float aa[8] = {a0.x, a0.y, a0.z, a0.w, a1.x, a1.y, a1.z, a1.w};
            float bb[8] = {b0.x, b0.y, b0.z, b0.w, b1.x, b1.y, b1.z, b1.w};
#pragma unroll
            for (int i = 0; i < 8; i++)
#pragma unroll
                for (int j = 0; j < 8; j++) acc[i][j] += aa[i] * bb[j];
        }
    }

    const float wbias = wb[0];
#pragma unroll
    for (int i = 0; i < 8; i++) {
        float sum = 0.f;
#pragma unroll
        for (int j = 0; j < 8; j++) {
            int col = (j < 4) ? (lane * 4 + j) : (128 + lane * 4 + (j - 4));
            sum += tanhf(acc[i][j] + qw[col]) * ws[col];
        }
#pragma unroll
        for (int off = 16; off; off >>= 1)
            sum += __shfl_xor_sync(0xffffffffu, sum, off);
        if (lane == 0)
            scores[row0 + warp * 8 + i] = sum + wbias;
    }
}

// ---------------------------------------------------------------------------
// Softmax over M=256 per row, in place. One block of 256 threads per row.
// ---------------------------------------------------------------------------
__global__ void __launch_bounds__(256) softmax_kernel(float* __restrict__ s)
{
    const int n = blockIdx.x, t = threadIdx.x;
    const int lane = t & 31, wrp = t >> 5;
    __shared__ float red[8];

    float v = s[n * Mm + t];
    float mx = v;
#pragma unroll
    for (int o = 16; o; o >>= 1) mx = fmaxf(mx, __shfl_xor_sync(0xffffffffu, mx, o));
    if (lane == 0) red[wrp] = mx;
    __syncthreads();
    if (t == 0) {
        float mm = red[0];
#pragma unroll
        for (int i = 1; i < 8; i++) mm = fmaxf(mm, red[i]);
        red[0] = mm;
    }
    __syncthreads();
    mx = red[0];
    __syncthreads();

    float e = expf(v - mx);
    float sum = e;
#pragma unroll
    for (int o = 16; o; o >>= 1) sum += __shfl_xor_sync(0xffffffffu, sum, o);
    if (lane == 0) red[wrp] = sum;
    __syncthreads();
    if (t == 0) {
        float ss = 0.f;
#pragma unroll
        for (int i = 0; i < 8; i++) ss += red[i];
        red[0] = ss;
    }
    __syncthreads();
    s[n * Mm + t] = e / red[0];
}

// ---------------------------------------------------------------------------
// context[n, d] = sum_m att[n, m] * memory[n, m, d].  One block per n.
// 512 threads = one d each; streams memory[n] fully coalesced.
// ---------------------------------------------------------------------------
__global__ void __launch_bounds__(512) context_kernel(
    const float* __restrict__ mem, const float* __restrict__ att,
    float* __restrict__ ctx)
{
    const int n = blockIdx.x, t = threadIdx.x;
    __shared__ float a_s[Mm];
    if (t < Mm) a_s[t] = att[n * Mm + t];
    __syncthreads();

    const float* mp = mem + (size_t)n * Mm * DMd + t;
    float a0 = 0.f, a1 = 0.f, a2 = 0.f, a3 = 0.f;
#pragma unroll 4
    for (int m = 0; m < Mm; m += 4) {
        a0 += a_s[m + 0] * mp[(size_t)(m + 0) * DMd];
        a1 += a_s[m + 1] * mp[(size_t)(m + 1) * DMd];
        a2 += a_s[m + 2] * mp[(size_t)(m + 2) * DMd];
        a3 += a_s[m + 3] * mp[(size_t)(m + 3) * DMd];
    }
    ctx[(size_t)n * DMd + t] = (a0 + a1) + (a2 + a3);
}

// ---------------------------------------------------------------------------
// Launch
// ---------------------------------------------------------------------------
extern "C" void kernel_launch(void* const* d_in, const int* in_sizes, int n_in,
                              void* d_out, int out_size)
{
    const float* query = (const float*)d_in[0];   // [N, DQ]
    const float* mem   = (const float*)d_in[1];   // [N, M, DM]
    const float* Ww    = (const float*)d_in[2];   // [DQ, P]
    const float* Wb    = (const float*)d_in[3];   // [P]
    const float* Uw    = (const float*)d_in[4];   // [DM, P]
    const float* Ub    = (const float*)d_in[5];   // [P]
    const float* ww    = (const float*)d_in[6];   // [P]
    const float* wb    = (const float*)d_in[7];   // [1]
    const float* Cw    = (const float*)d_in[8];   // [DQ+DM, DQ]
    const float* Cb    = (const float*)d_in[9];   // [DQ]
    float* out = (float*)d_out;

    float *qb, *sc, *ctx;
    cudaGetSymbolAddress((void**)&qb,  g_q);
    cudaGetSymbolAddress((void**)&sc,  g_sc);
    cudaGetSymbolAddress((void**)&ctx, g_ctx);

    // 1) q = query @ W_att + b            [2048, 256]
    gemm64_kernel<false, false><<<dim3(Pp / 64, Nn / 64), 256>>>(
        query, nullptr, Ww, Wb, qb, DQd, Pp);

    // 2) scores[n,m] (big GEMM + tanh-dot epilogue)
    scores_kernel<<<(Nn * Mm) / 128, 512>>>(mem, Uw, Ub, ww, wb, qb, sc);

    // 3) softmax over M (in place -> att)
    softmax_kernel<<<Nn, 256>>>(sc);

    // 4) context = att @ memory           [2048, 512]
    context_kernel<<<Nn, 512>>>(mem, sc, ctx);

    // 5) out = relu([context | query] @ W_cat + b)   [2048, 512]
    gemm64_kernel<true, true><<<dim3(DQd / 64, Nn / 64), 256>>>(
        ctx, query, Cw, Cb, out, DQd + DMd, DQd);
}

// round 4
// speedup vs baseline: 2.7679x; 2.7679x over previous
#include <cuda_runtime.h>
#include <cuda_bf16.h>
#include <cstdint>

// Problem constants
#define Nn   2048
#define Mm   256
#define DQd  512
#define DMd  512
#define Pp   256

// Scratch (device globals; no allocations allowed)
__device__ float g_q[Nn * Pp];            // q projection  [N, P]
__device__ float g_sc[Nn * Mm];           // scores -> att [N, M]
__device__ float g_ctx[Nn * DMd];         // context       [N, DM]
__device__ __nv_bfloat16 g_Ubf[Pp * DMd]; // U transposed  [P, DM] bf16

// ---------------------------------------------------------------------------
// PTX helpers (sm_80-level only: mma.sync / ldmatrix / cp.async)
// ---------------------------------------------------------------------------
__device__ __forceinline__ uint32_t smem_to_u32(const void* p) {
    uint32_t a;
    asm("{ .reg .u64 t; cvta.to.shared.u64 t, %1; cvt.u32.u64 %0, t; }" : "=r"(a) : "l"(p));
    return a;
}

__device__ __forceinline__ void ldm_x4(uint32_t& r0, uint32_t& r1, uint32_t& r2,
                                       uint32_t& r3, uint32_t addr) {
    asm volatile("ldmatrix.sync.aligned.m8n8.x4.shared.b16 {%0,%1,%2,%3}, [%4];"
                 : "=r"(r0), "=r"(r1), "=r"(r2), "=r"(r3) : "r"(addr));
}

__device__ __forceinline__ void mma_bf16(float* d, const uint32_t* a, const uint32_t* b) {
    asm volatile(
        "mma.sync.aligned.m16n8k16.row.col.f32.bf16.bf16.f32 "
        "{%0,%1,%2,%3}, {%4,%5,%6,%7}, {%8,%9}, {%0,%1,%2,%3};"
        : "+f"(d[0]), "+f"(d[1]), "+f"(d[2]), "+f"(d[3])
        : "r"(a[0]), "r"(a[1]), "r"(a[2]), "r"(a[3]), "r"(b[0]), "r"(b[1]));
}

#define CP_ASYNC_16(dst, src) \
    asm volatile("cp.async.cg.shared.global [%0], [%1], 16;" :: "r"(dst), "l"(src) : "memory")
#define CP_ASYNC_COMMIT()   asm volatile("cp.async.commit_group;" ::: "memory")
#define CP_ASYNC_WAIT_ALL() asm volatile("cp.async.wait_group 0;" ::: "memory")

// scores kernel smem layout (bytes). Rows padded to 80B (conflict-free ldmatrix).
static constexpr int SM_A0 = 0;          // 128 rows x 80B = 10240
static constexpr int SM_A1 = 10240;
static constexpr int SM_B0 = 20480;      // 256 rows x 80B = 20480
static constexpr int SM_B1 = 40960;
static constexpr int SM_QW = 61440;      // 256 f32
static constexpr int SM_WS = 62464;      // 256 f32
static constexpr int SM_RS = 63488;      // 128 f32 rowsums
static constexpr int SM_TOTAL = 64000;

// ---------------------------------------------------------------------------
// U[k][p] -> Ubf[p][k] bf16 (tiny, one-time)
// ---------------------------------------------------------------------------
__global__ void __launch_bounds__(256) prep_u_kernel(
    const float* __restrict__ U, __nv_bfloat16* __restrict__ Ubf)
{
    int k = blockIdx.x, p = threadIdx.x;
    Ubf[p * DMd + k] = __float2bfloat16(U[k * Pp + p]);
}

// ---------------------------------------------------------------------------
// Generic 64x64-tile fp32 GEMM: C = act(A @ B + bias)
// ---------------------------------------------------------------------------
template <bool CAT, bool RELU>
__global__ void __launch_bounds__(256, 2) gemm64_kernel(
    const float* __restrict__ A0, const float* __restrict__ A1,
    const float* __restrict__ B, const float* __restrict__ bias,
    float* __restrict__ C, int K, int Ncols)
{
    __shared__ float As[16][68];
    __shared__ float Bs[16][64];

    const int t = threadIdx.x;
    const int row0 = blockIdx.y * 64;
    const int col0 = blockIdx.x * 64;
    const int tx = t & 15, ty = t >> 4;
    const int lr = t >> 2, kc = t & 3;
    const int kb = t >> 4, cc = t & 15;

    float acc[4][4];
#pragma unroll
    for (int i = 0; i < 4; i++)
#pragma unroll
        for (int j = 0; j < 4; j++) acc[i][j] = 0.f;

    for (int k0 = 0; k0 < K; k0 += 16) {
        const int kg = k0 + kc * 4;
        const float* asrc;
        if (CAT) {
            asrc = (kg < 512) ? (A0 + (size_t)(row0 + lr) * 512 + kg)
                              : (A1 + (size_t)(row0 + lr) * 512 + (kg - 512));
        } else {
            asrc = A0 + (size_t)(row0 + lr) * K + kg;
        }
        float4 av = *(const float4*)asrc;
        float4 bv = *(const float4*)(B + (size_t)(k0 + kb) * Ncols + col0 + cc * 4);

        __syncthreads();
        As[kc * 4 + 0][lr] = av.x;
        As[kc * 4 + 1][lr] = av.y;
        As[kc * 4 + 2][lr] = av.z;
        As[kc * 4 + 3][lr] = av.w;
        *(float4*)&Bs[kb][cc * 4] = bv;
        __syncthreads();

#pragma unroll
        for (int k = 0; k < 16; k++) {
            float4 a = *(const float4*)&As[k][ty * 4];
            float4 b = *(const float4*)&Bs[k][tx * 4];
            float aa[4] = {a.x, a.y, a.z, a.w};
            float bb[4] = {b.x, b.y, b.z, b.w};
#pragma unroll
            for (int i = 0; i < 4; i++)
#pragma unroll
                for (int j = 0; j < 4; j++) acc[i][j] += aa[i] * bb[j];
        }
    }

#pragma unroll
    for (int i = 0; i < 4; i++)
#pragma unroll
        for (int j = 0; j < 4; j++) {
            int c = col0 + tx * 4 + j;
            float v = acc[i][j] + bias[c];
            if (RELU) v = fmaxf(v, 0.f);
            C[(size_t)(row0 + ty * 4 + i) * Ncols + c] = v;
        }
}

// ---------------------------------------------------------------------------
// Scores via mma.sync (HMMA bf16): CTA = 128 rows x 256 cols, BK=32, K=512.
// A = mem fp32 (LDG -> cvt bf16 -> STS), B = Ubf [P][DM] via cp.async.
// 512 threads: warp grid 4(m) x 4(n); warp tile 32x64.
// Epilogue: scores[row] = sum_p tanh(D + q[n,p] + Ub[p]) * w[p]   (wb dropped:
// per-row constant is softmax-invariant).
// ---------------------------------------------------------------------------
__global__ void __launch_bounds__(512) scores_mma_kernel(
    const float* __restrict__ mem, const __nv_bfloat16* __restrict__ Ubf,
    const float* __restrict__ Ub, const float* __restrict__ w,
    const float* __restrict__ q, float* __restrict__ scores)
{
    extern __shared__ char smem[];
    const uint32_t sb = smem_to_u32(smem);
    const int t = threadIdx.x;
    const int wid = t >> 5, lane = t & 31;
    const int wm = wid >> 2, wn = wid & 3;     // warp row/col in 4x4 grid
    const int row0 = blockIdx.x * 128;         // flattened n*M + m
    const int n = row0 >> 8;                   // tile never crosses n

    float* qw = (float*)(smem + SM_QW);
    float* ws = (float*)(smem + SM_WS);
    float* rowsum = (float*)(smem + SM_RS);

    if (t < 256) {
        qw[t] = q[n * Pp + t] + Ub[t];
        ws[t] = w[t];
    }
    if (t < 128) rowsum[t] = 0.f;

    float acc[2][8][4];
#pragma unroll
    for (int mt = 0; mt < 2; mt++)
#pragma unroll
        for (int nt = 0; nt < 8; nt++)
#pragma unroll
            for (int j = 0; j < 4; j++) acc[mt][nt][j] = 0.f;

    // A loader indices: 1024 float4 per stage, 2 per thread
    const int ar0 = t >> 3, ag0 = t & 7;               // idx = t
    const int ar1 = (t + 512) >> 3, ag1 = t & 7;       // idx = t + 512
    // B loader indices: 1024 x 16B chunks, 2 per thread
    const int br0 = t >> 2, bg0 = t & 3;
    const int br1 = (t + 512) >> 2, bg1 = t & 3;

    auto ldg_a = [&](int c, float4& v0, float4& v1) {
        const float* base = mem + (size_t)row0 * DMd + c * 32;
        v0 = *(const float4*)(base + (size_t)ar0 * DMd + ag0 * 4);
        v1 = *(const float4*)(base + (size_t)ar1 * DMd + ag1 * 4);
    };
    auto sts_a = [&](int c, const float4& v0, const float4& v1) {
        const uint32_t ab = sb + ((c & 1) ? SM_A1 : SM_A0);
        __nv_bfloat162 h0 = __floats2bfloat162_rn(v0.x, v0.y);
        __nv_bfloat162 h1 = __floats2bfloat162_rn(v0.z, v0.w);
        uint32_t dst = ab + ar0 * 80 + ag0 * 8;
        asm volatile("st.shared.v2.b32 [%0], {%1,%2};" ::
                     "r"(dst), "r"(*(uint32_t*)&h0), "r"(*(uint32_t*)&h1) : "memory");
        __nv_bfloat162 h2 = __floats2bfloat162_rn(v1.x, v1.y);
        __nv_bfloat162 h3 = __floats2bfloat162_rn(v1.z, v1.w);
        dst = ab + ar1 * 80 + ag1 * 8;
        asm volatile("st.shared.v2.b32 [%0], {%1,%2};" ::
                     "r"(dst), "r"(*(uint32_t*)&h2), "r"(*(uint32_t*)&h3) : "memory");
    };
    auto issue_b = [&](int c) {
        const uint32_t bb = sb + ((c & 1) ? SM_B1 : SM_B0);
        const __nv_bfloat16* base = Ubf + c * 32;
        CP_ASYNC_16(bb + br0 * 80 + bg0 * 16, base + (size_t)br0 * DMd + bg0 * 8);
        CP_ASYNC_16(bb + br1 * 80 + bg1 * 16, base + (size_t)br1 * DMd + bg1 * 8);
        CP_ASYNC_COMMIT();
    };

    // preamble: stage 0
    {
        float4 v0, v1;
        ldg_a(0, v0, v1);
        issue_b(0);
        sts_a(0, v0, v1);
    }

    const int mat = lane >> 3, mj = lane & 7;

    float4 p0, p1;
    for (int c = 0; c < 16; c++) {
        CP_ASYNC_WAIT_ALL();
        __syncthreads();                      // stage c ready; buffer (c+1)&1 free

        if (c < 15) {
            ldg_a(c + 1, p0, p1);             // overlap with compute
            issue_b(c + 1);
        }

        const uint32_t ab = sb + ((c & 1) ? SM_A1 : SM_A0);
        const uint32_t bb = sb + ((c & 1) ? SM_B1 : SM_B0);
#pragma unroll
        for (int ks = 0; ks < 2; ks++) {
            uint32_t a[2][4];
#pragma unroll
            for (int mt = 0; mt < 2; mt++) {
                const int r = wm * 32 + mt * 16 + (mat & 1) * 8 + mj;
                ldm_x4(a[mt][0], a[mt][1], a[mt][2], a[mt][3],
                       ab + r * 80 + (ks * 2 + (mat >> 1)) * 16);
            }
            uint32_t b[8][2];
#pragma unroll
            for (int p = 0; p < 4; p++) {
                const int nr = wn * 64 + (p * 2 + (mat >> 1)) * 8 + mj;
                ldm_x4(b[2 * p][0], b[2 * p][1], b[2 * p + 1][0], b[2 * p + 1][1],
                       bb + nr * 80 + (ks * 2 + (mat & 1)) * 16);
            }
#pragma unroll
            for (int mt = 0; mt < 2; mt++)
#pragma unroll
                for (int nt = 0; nt < 8; nt++)
                    mma_bf16(acc[mt][nt], a[mt], b[nt]);
        }
        __syncthreads();                      // done reading buffer c&1
        if (c < 15) sts_a(c + 1, p0, p1);
    }

    // ---- epilogue: tanh-dot + row reduction ----
    const int g = lane >> 2, q4 = lane & 3;
    float sums[4];
#pragma unroll
    for (int mt = 0; mt < 2; mt++)
#pragma unroll
        for (int h = 0; h < 2; h++) {
            float s = 0.f;
#pragma unroll
            for (int nt = 0; nt < 8; nt++)
#pragma unroll
                for (int jj = 0; jj < 2; jj++) {
                    const int col = wn * 64 + nt * 8 + q4 * 2 + jj;
                    s += tanhf(acc[mt][nt][h * 2 + jj] + qw[col]) * ws[col];
                }
            sums[mt * 2 + h] = s;
        }
#pragma unroll
    for (int i = 0; i < 4; i++) {
        sums[i] += __shfl_xor_sync(0xffffffffu, sums[i], 1);
        sums[i] += __shfl_xor_sync(0xffffffffu, sums[i], 2);
    }
    if (q4 == 0) {
#pragma unroll
        for (int mt = 0; mt < 2; mt++)
#pragma unroll
            for (int h = 0; h < 2; h++)
                atomicAdd(&rowsum[wm * 32 + mt * 16 + h * 8 + g], sums[mt * 2 + h]);
    }
    __syncthreads();
    if (t < 128) scores[row0 + t] = rowsum[t];
}

// ---------------------------------------------------------------------------
// Softmax over M=256 per row, in place.
// ---------------------------------------------------------------------------
__global__ void __launch_bounds__(256) softmax_kernel(float* __restrict__ s)
{
    const int n = blockIdx.x, t = threadIdx.x;
    const int lane = t & 31, wrp = t >> 5;
    __shared__ float red[8];

    float v = s[n * Mm + t];
    float mx = v;
#pragma unroll
    for (int o = 16; o; o >>= 1) mx = fmaxf(mx, __shfl_xor_sync(0xffffffffu, mx, o));
    if (lane == 0) red[wrp] = mx;
    __syncthreads();
    if (t == 0) {
        float mm = red[0];
#pragma unroll
        for (int i = 1; i < 8; i++) mm = fmaxf(mm, red[i]);
        red[0] = mm;
    }
    __syncthreads();
    mx = red[0];
    __syncthreads();

    float e = expf(v - mx);
    float sum = e;
#pragma unroll
    for (int o = 16; o; o >>= 1) sum += __shfl_xor_sync(0xffffffffu, sum, o);
    if (lane == 0) red[wrp] = sum;
    __syncthreads();
    if (t == 0) {
        float ss = 0.f;
#pragma unroll
        for (int i = 0; i < 8; i++) ss += red[i];
        red[0] = ss;
    }
    __syncthreads();
    s[n * Mm + t] = e / red[0];
}

// ---------------------------------------------------------------------------
// context[n, d] = sum_m att[n, m] * memory[n, m, d]. One block per n (fp32).
// ---------------------------------------------------------------------------
__global__ void __launch_bounds__(512) context_kernel(
    const float* __restrict__ mem, const float* __restrict__ att,
    float* __restrict__ ctx)
{
    const int n = blockIdx.x, t = threadIdx.x;
    __shared__ float a_s[Mm];
    if (t < Mm) a_s[t] = att[n * Mm + t];
    __syncthreads();

    const float* mp = mem + (size_t)n * Mm * DMd + t;
    float a0 = 0.f, a1 = 0.f, a2 = 0.f, a3 = 0.f;
#pragma unroll 4
    for (int m = 0; m < Mm; m += 4) {
        a0 += a_s[m + 0] * mp[(size_t)(m + 0) * DMd];
        a1 += a_s[m + 1] * mp[(size_t)(m + 1) * DMd];
        a2 += a_s[m + 2] * mp[(size_t)(m + 2) * DMd];
        a3 += a_s[m + 3] * mp[(size_t)(m + 3) * DMd];
    }
    ctx[(size_t)n * DMd + t] = (a0 + a1) + (a2 + a3);
}

// ---------------------------------------------------------------------------
// Launch
// ---------------------------------------------------------------------------
extern "C" void kernel_launch(void* const* d_in, const int* in_sizes, int n_in,
                              void* d_out, int out_size)
{
    const float* query = (const float*)d_in[0];   // [N, DQ]
    const float* mem   = (const float*)d_in[1];   // [N, M, DM]
    const float* Ww    = (const float*)d_in[2];   // [DQ, P]
    const float* Wb    = (const float*)d_in[3];   // [P]
    const float* Uw    = (const float*)d_in[4];   // [DM, P]
    const float* Ub    = (const float*)d_in[5];   // [P]
    const float* ww    = (const float*)d_in[6];   // [P]
    // d_in[7] = w_att_b: dropped (softmax-invariant per-row constant)
    const float* Cw    = (const float*)d_in[8];   // [DQ+DM, DQ]
    const float* Cb    = (const float*)d_in[9];   // [DQ]
    float* out = (float*)d_out;

    float *qb, *sc, *ctx;
    __nv_bfloat16* Ubf;
    cudaGetSymbolAddress((void**)&qb,  g_q);
    cudaGetSymbolAddress((void**)&sc,  g_sc);
    cudaGetSymbolAddress((void**)&ctx, g_ctx);
    cudaGetSymbolAddress((void**)&Ubf, g_Ubf);

    cudaFuncSetAttribute(scores_mma_kernel,
                         cudaFuncAttributeMaxDynamicSharedMemorySize, SM_TOTAL);

    // 1) U -> transposed bf16 [P, DM]
    prep_u_kernel<<<DMd, Pp>>>(Uw, Ubf);

    // 2) q = query @ W_att + b   [2048, 256]
    gemm64_kernel<false, false><<<dim3(Pp / 64, Nn / 64), 256>>>(
        query, nullptr, Ww, Wb, qb, DQd, Pp);

    // 3) scores via HMMA bf16 + fused tanh-dot epilogue
    scores_mma_kernel<<<(Nn * Mm) / 128, 512, SM_TOTAL>>>(
        mem, Ubf, Ub, ww, qb, sc);

    // 4) softmax over M (in place -> att)
    softmax_kernel<<<Nn, 256>>>(sc);

    // 5) context = att @ memory   [2048, 512]
    context_kernel<<<Nn, 512>>>(mem, sc, ctx);

    // 6) out = relu([context | query] @ W_cat + b)   [2048, 512]
    gemm64_kernel<true, true><<<dim3(DQd / 64, Nn / 64), 256>>>(
        ctx, query, Cw, Cb, out, DQd + DMd, DQd);
}